// round 2
// baseline (speedup 1.0000x reference)
#include <cuda_runtime.h>

#define HID   128
#define MAXN  50000
#define MAXE  600000
#define STRX  132              // padded smem row stride (words)
#define TILE_N 64
#define MLP_SMEM ((TILE_N*STRX + 128*STRX + TILE_N*STRX) * 4)

// -------- device scratch (static: allocation-free) --------
__device__ int   d_deg[MAXN];
__device__ int   d_rowptr[MAXN + 1];
__device__ int   d_cursor[MAXN];
__device__ int   d_eid[MAXE];
__device__ float d_bufA[MAXN * HID];
__device__ float d_bufB[MAXN * HID];

// numerically-stable softplus: max(x,0) + log(1+exp(-|x|))
__device__ __forceinline__ float sp(float v) {
    float e = __expf(-fabsf(v));
    return fmaxf(v, 0.0f) + __logf(1.0f + e);
}

// -------- CSR build --------
__global__ void clear_deg_kernel(int n) {
    int i = blockIdx.x * blockDim.x + threadIdx.x;
    if (i < n) d_deg[i] = 0;
}

__global__ void hist_kernel(const int* __restrict__ dst, int E) {
    int e = blockIdx.x * blockDim.x + threadIdx.x;
    if (e < E) atomicAdd(&d_deg[dst[e]], 1);
}

__global__ void scan_kernel(int n) {
    __shared__ int buf[1024];
    __shared__ int carry;
    int t = threadIdx.x;
    if (t == 0) { carry = 0; d_rowptr[0] = 0; }
    __syncthreads();
    for (int base = 0; base < n; base += 1024) {
        int idx = base + t;
        int v = (idx < n) ? d_deg[idx] : 0;
        buf[t] = v;
        __syncthreads();
        // Hillis-Steele inclusive scan
        #pragma unroll
        for (int off = 1; off < 1024; off <<= 1) {
            int x = (t >= off) ? buf[t - off] : 0;
            __syncthreads();
            buf[t] += x;
            __syncthreads();
        }
        int incl = buf[t] + carry;
        if (idx < n) {
            d_rowptr[idx + 1] = incl;
            d_cursor[idx]     = incl - v;   // exclusive prefix = write cursor
        }
        __syncthreads();
        if (t == 1023) carry = incl;
        __syncthreads();
    }
}

__global__ void scatter_kernel(const int* __restrict__ dst, int E) {
    int e = blockIdx.x * blockDim.x + threadIdx.x;
    if (e < E) {
        int p = atomicAdd(&d_cursor[dst[e]], 1);
        d_eid[p] = e;
    }
}

// -------- edge aggregation: warp per node, out = x + sum_e softplus(x[src]+ea[e]) --------
__global__ void agg_kernel(const float* __restrict__ x, const float* __restrict__ ea,
                           const int* __restrict__ src, float* __restrict__ out, int N) {
    int warp = (blockIdx.x * blockDim.x + threadIdx.x) >> 5;
    int lane = threadIdx.x & 31;
    if (warp >= N) return;
    const float4* x4  = (const float4*)x;
    const float4* ea4 = (const float4*)ea;
    float4 acc = x4[(size_t)warp * 32 + lane];   // (1+eps)*x, eps=0
    int beg = d_rowptr[warp];
    int end = d_rowptr[warp + 1];
    for (int j = beg; j < end; j++) {
        int e = d_eid[j];
        int s = __ldg(&src[e]);
        float4 xv = x4[(size_t)s * 32 + lane];
        float4 ev = ea4[(size_t)e * 32 + lane];
        acc.x += sp(xv.x + ev.x);
        acc.y += sp(xv.y + ev.y);
        acc.z += sp(xv.z + ev.z);
        acc.w += sp(xv.w + ev.w);
    }
    ((float4*)out)[(size_t)warp * 32 + lane] = acc;
}

// -------- fused 2-layer MLP: y = sp(in@W1^T+b1)@W2^T+b2 [, sp] --------
__global__ __launch_bounds__(256) void mlp_kernel(
    const float* __restrict__ xin, float* __restrict__ xout,
    const float* __restrict__ W1, const float* __restrict__ B1,
    const float* __restrict__ W2, const float* __restrict__ B2,
    int N, int out_softplus)
{
    extern __shared__ float sm[];
    float* sX = sm;                                 // TILE_N x STRX
    float* sW = sm + TILE_N * STRX;                 // 128 x STRX
    float* sH = sm + TILE_N * STRX + 128 * STRX;    // TILE_N x STRX

    int t  = threadIdx.x;
    int n0 = blockIdx.x * TILE_N;
    int tx = t & 15;         // covers 8 output cols: j = tx + 16*u
    int ty = t >> 4;         // covers 4 rows: n = ty*4 + ni

    // load X tile
    for (int i = t; i < TILE_N * 32; i += 256) {
        int r = i >> 5, c = i & 31;
        float4 v = make_float4(0.f, 0.f, 0.f, 0.f);
        if (n0 + r < N) v = ((const float4*)xin)[(size_t)(n0 + r) * 32 + c];
        *(float4*)&sX[r * STRX + c * 4] = v;
    }
    // load W1
    for (int i = t; i < 128 * 32; i += 256) {
        int r = i >> 5, c = i & 31;
        *(float4*)&sW[r * STRX + c * 4] = ((const float4*)W1)[i];
    }
    __syncthreads();

    float acc[4][8];
    #pragma unroll
    for (int u = 0; u < 8; u++) {
        float b = __ldg(&B1[tx + 16 * u]);
        #pragma unroll
        for (int ni = 0; ni < 4; ni++) acc[ni][u] = b;
    }
    for (int k = 0; k < 128; k += 4) {
        float4 a[4], b[8];
        #pragma unroll
        for (int ni = 0; ni < 4; ni++) a[ni] = *(const float4*)&sX[(ty * 4 + ni) * STRX + k];
        #pragma unroll
        for (int u = 0; u < 8; u++) b[u] = *(const float4*)&sW[(tx + 16 * u) * STRX + k];
        #pragma unroll
        for (int ni = 0; ni < 4; ni++) {
            #pragma unroll
            for (int u = 0; u < 8; u++) {
                acc[ni][u] = fmaf(a[ni].x, b[u].x, acc[ni][u]);
                acc[ni][u] = fmaf(a[ni].y, b[u].y, acc[ni][u]);
                acc[ni][u] = fmaf(a[ni].z, b[u].z, acc[ni][u]);
                acc[ni][u] = fmaf(a[ni].w, b[u].w, acc[ni][u]);
            }
        }
    }
    #pragma unroll
    for (int ni = 0; ni < 4; ni++)
        #pragma unroll
        for (int u = 0; u < 8; u++)
            sH[(ty * 4 + ni) * STRX + tx + 16 * u] = sp(acc[ni][u]);
    __syncthreads();

    // stage 2: reload W2 into sW
    for (int i = t; i < 128 * 32; i += 256) {
        int r = i >> 5, c = i & 31;
        *(float4*)&sW[r * STRX + c * 4] = ((const float4*)W2)[i];
    }
    __syncthreads();

    #pragma unroll
    for (int u = 0; u < 8; u++) {
        float b = __ldg(&B2[tx + 16 * u]);
        #pragma unroll
        for (int ni = 0; ni < 4; ni++) acc[ni][u] = b;
    }
    for (int k = 0; k < 128; k += 4) {
        float4 a[4], b[8];
        #pragma unroll
        for (int ni = 0; ni < 4; ni++) a[ni] = *(const float4*)&sH[(ty * 4 + ni) * STRX + k];
        #pragma unroll
        for (int u = 0; u < 8; u++) b[u] = *(const float4*)&sW[(tx + 16 * u) * STRX + k];
        #pragma unroll
        for (int ni = 0; ni < 4; ni++) {
            #pragma unroll
            for (int u = 0; u < 8; u++) {
                acc[ni][u] = fmaf(a[ni].x, b[u].x, acc[ni][u]);
                acc[ni][u] = fmaf(a[ni].y, b[u].y, acc[ni][u]);
                acc[ni][u] = fmaf(a[ni].z, b[u].z, acc[ni][u]);
                acc[ni][u] = fmaf(a[ni].w, b[u].w, acc[ni][u]);
            }
        }
    }
    // stage results in sX (done reading it), then coalesced store
    #pragma unroll
    for (int ni = 0; ni < 4; ni++)
        #pragma unroll
        for (int u = 0; u < 8; u++) {
            float v = acc[ni][u];
            if (out_softplus) v = sp(v);
            sX[(ty * 4 + ni) * STRX + tx + 16 * u] = v;
        }
    __syncthreads();
    for (int i = t; i < TILE_N * 32; i += 256) {
        int r = i >> 5, c = i & 31;
        if (n0 + r < N)
            ((float4*)xout)[(size_t)(n0 + r) * 32 + c] = *(float4*)&sX[r * STRX + c * 4];
    }
}

// -------- graph pooling: block per graph, batch is sorted --------
__device__ __forceinline__ int lbound(const int* __restrict__ a, int n, int key) {
    int lo = 0, hi = n;
    while (lo < hi) {
        int mid = (lo + hi) >> 1;
        if (a[mid] < key) lo = mid + 1; else hi = mid;
    }
    return lo;
}

__global__ void pool_kernel(const float* __restrict__ nf, const int* __restrict__ batch,
                            float* __restrict__ gf, int N, int G) {
    int g = blockIdx.x;
    int t = threadIdx.x;   // 128 threads, one feature each
    int lo = lbound(batch, N, g);
    int hi = lbound(batch, N, g + 1);
    float acc = 0.0f;
    for (int n = lo; n < hi; n++) acc += nf[(size_t)n * HID + t];
    gf[(size_t)g * HID + t] = acc;
}

// -------- launch --------
extern "C" void kernel_launch(void* const* d_in, const int* in_sizes, int n_in,
                              void* d_out, int out_size) {
    const float* node_attr = (const float*)d_in[0];
    const float* edge_attr = (const float*)d_in[1];
    const int*   eidx      = (const int*)d_in[2];
    const int*   batch     = (const int*)d_in[3];
    const float* W1        = (const float*)d_in[4];
    const float* B1        = (const float*)d_in[5];
    const float* W2        = (const float*)d_in[6];
    const float* B2        = (const float*)d_in[7];

    int N = in_sizes[0] / HID;
    int E = in_sizes[1] / HID;
    int G = out_size / HID - N;

    const int* src = eidx;       // edge_index[0]
    const int* dst = eidx + E;   // edge_index[1]

    float* gf = (float*)d_out;                       // [G,128] graph_feature
    float* nf = (float*)d_out + (size_t)G * HID;     // [N,128] node_feature

    float *bufA, *bufB;
    cudaGetSymbolAddress((void**)&bufA, d_bufA);
    cudaGetSymbolAddress((void**)&bufB, d_bufB);

    cudaFuncSetAttribute(mlp_kernel, cudaFuncAttributeMaxDynamicSharedMemorySize, MLP_SMEM);

    // CSR build (edge structure is layer-invariant)
    clear_deg_kernel<<<(N + 255) / 256, 256>>>(N);
    hist_kernel<<<(E + 255) / 256, 256>>>(dst, E);
    scan_kernel<<<1, 1024>>>(N);
    scatter_kernel<<<(E + 255) / 256, 256>>>(dst, E);

    const float* x = node_attr;
    for (int l = 0; l < 3; l++) {
        agg_kernel<<<(N * 32 + 255) / 256, 256>>>(x, edge_attr, src, bufB, N);
        float* out = (l == 2) ? nf : bufA;
        mlp_kernel<<<(N + TILE_N - 1) / TILE_N, 256, MLP_SMEM>>>(
            bufB, out, W1 + (size_t)l * HID * HID, B1 + (size_t)l * HID,
            W2 + (size_t)l * HID * HID, B2 + (size_t)l * HID, N, (l < 2) ? 1 : 0);
        x = bufA;
    }
    pool_kernel<<<G, HID>>>(nf, batch, gf, N, G);
}

// round 3
// speedup vs baseline: 1.6023x; 1.6023x over previous
#include <cuda_runtime.h>
#include <stdint.h>

#define HID   128
#define MAXN  50000
#define MAXE  600000

// -------- device scratch (static: allocation-free) --------
__device__ int   d_deg[MAXN];
__device__ int   d_rowptr[MAXN + 1];
__device__ int   d_cursor[MAXN];
__device__ int   d_eid[MAXE];
__device__ int   d_esrc[MAXE];
__device__ float d_bufA[MAXN * HID];
__device__ float d_bufB[MAXN * HID];

// numerically-stable softplus
__device__ __forceinline__ float sp(float v) {
    float e = __expf(-fabsf(v));
    return fmaxf(v, 0.0f) + __logf(1.0f + e);
}

__device__ __forceinline__ uint32_t f2tf32(float f) {
    uint32_t r;
    asm("cvt.rna.tf32.f32 %0, %1;" : "=r"(r) : "f"(f));
    return r;
}

__device__ __forceinline__ void mma8(float* c,
    uint32_t a0, uint32_t a1, uint32_t a2, uint32_t a3,
    uint32_t b0, uint32_t b1)
{
    asm volatile(
        "mma.sync.aligned.m16n8k8.row.col.f32.tf32.tf32.f32 "
        "{%0,%1,%2,%3}, {%4,%5,%6,%7}, {%8,%9}, {%0,%1,%2,%3};"
        : "+f"(c[0]), "+f"(c[1]), "+f"(c[2]), "+f"(c[3])
        : "r"(a0), "r"(a1), "r"(a2), "r"(a3), "r"(b0), "r"(b1));
}

// -------- CSR build --------
__global__ void clear_deg_kernel(int n) {
    int i = blockIdx.x * blockDim.x + threadIdx.x;
    if (i < n) d_deg[i] = 0;
}

__global__ void hist_kernel(const int* __restrict__ dst, int E) {
    int e = blockIdx.x * blockDim.x + threadIdx.x;
    if (e < E) atomicAdd(&d_deg[dst[e]], 1);
}

// warp-shuffle block scan, 1024 threads, serial over tiles
__global__ void scan_kernel(int n) {
    __shared__ int wsum[32];
    __shared__ int carry;
    int t = threadIdx.x;
    int lane = t & 31, w = t >> 5;
    if (t == 0) { carry = 0; d_rowptr[0] = 0; }
    __syncthreads();
    for (int base = 0; base < n; base += 1024) {
        int idx = base + t;
        int v = (idx < n) ? d_deg[idx] : 0;
        int x = v;
        #pragma unroll
        for (int off = 1; off < 32; off <<= 1) {
            int u = __shfl_up_sync(0xFFFFFFFF, x, off);
            if (lane >= off) x += u;
        }
        if (lane == 31) wsum[w] = x;
        __syncthreads();
        if (w == 0) {
            int s = wsum[lane];
            #pragma unroll
            for (int off = 1; off < 32; off <<= 1) {
                int u = __shfl_up_sync(0xFFFFFFFF, s, off);
                if (lane >= off) s += u;
            }
            wsum[lane] = s;
        }
        __syncthreads();
        int incl = x + (w ? wsum[w - 1] : 0) + carry;
        if (idx < n) {
            d_rowptr[idx + 1] = incl;
            d_cursor[idx]     = incl - v;
        }
        __syncthreads();
        if (t == 1023) carry = incl;
        __syncthreads();
    }
}

__global__ void scatter_kernel(const int* __restrict__ srcp, const int* __restrict__ dst, int E) {
    int e = blockIdx.x * blockDim.x + threadIdx.x;
    if (e < E) {
        int p = atomicAdd(&d_cursor[dst[e]], 1);
        d_eid[p]  = e;
        d_esrc[p] = srcp[e];
    }
}

// -------- edge aggregation: warp per node --------
__global__ void agg_kernel(const float* __restrict__ x, const float* __restrict__ ea,
                           float* __restrict__ out, int N) {
    int warp = (blockIdx.x * blockDim.x + threadIdx.x) >> 5;
    int lane = threadIdx.x & 31;
    if (warp >= N) return;
    const float4* x4  = (const float4*)x;
    const float4* ea4 = (const float4*)ea;
    float4 acc = x4[(size_t)warp * 32 + lane];
    int beg = d_rowptr[warp];
    int end = d_rowptr[warp + 1];
    int j = beg;
    for (; j + 1 < end; j += 2) {
        int e0 = d_eid[j],  s0 = d_esrc[j];
        int e1 = d_eid[j+1], s1 = d_esrc[j+1];
        float4 xv0 = x4[(size_t)s0 * 32 + lane];
        float4 ev0 = ea4[(size_t)e0 * 32 + lane];
        float4 xv1 = x4[(size_t)s1 * 32 + lane];
        float4 ev1 = ea4[(size_t)e1 * 32 + lane];
        acc.x += sp(xv0.x + ev0.x) + sp(xv1.x + ev1.x);
        acc.y += sp(xv0.y + ev0.y) + sp(xv1.y + ev1.y);
        acc.z += sp(xv0.z + ev0.z) + sp(xv1.z + ev1.z);
        acc.w += sp(xv0.w + ev0.w) + sp(xv1.w + ev1.w);
    }
    if (j < end) {
        int e = d_eid[j], s = d_esrc[j];
        float4 xv = x4[(size_t)s * 32 + lane];
        float4 ev = ea4[(size_t)e * 32 + lane];
        acc.x += sp(xv.x + ev.x);
        acc.y += sp(xv.y + ev.y);
        acc.z += sp(xv.z + ev.z);
        acc.w += sp(xv.w + ev.w);
    }
    ((float4*)out)[(size_t)warp * 32 + lane] = acc;
}

// -------- fused 2-layer MLP on tensor cores (tf32 mma.sync) --------
// Block: 256 threads = 8 warps (4 M-groups x 2 N-groups); block tile 128x128.
// Warp tile: 32 rows x 64 cols = 2 m16-tiles x 8 n8-tiles, K loop 16 x k8.
#define MSTR 132
#define MLP_SMEM (2 * 128 * MSTR * 4)

__global__ __launch_bounds__(256) void mlp_tc_kernel(
    const float* __restrict__ xin, float* __restrict__ xout,
    const float* __restrict__ W1, const float* __restrict__ B1,
    const float* __restrict__ W2, const float* __restrict__ B2,
    int N, int out_softplus)
{
    extern __shared__ uint32_t smu[];
    uint32_t* sX = smu;                 // 128 x MSTR (tf32 bits)
    uint32_t* sW = smu + 128 * MSTR;    // 128 x MSTR

    int t    = threadIdx.x;
    int lane = t & 31;
    int wid  = t >> 5;
    int wm   = wid & 3;    // 0..3 -> 32-row group
    int wn   = wid >> 2;   // 0..1 -> 64-col group
    int g    = lane >> 2;  // 0..7
    int q    = lane & 3;   // 0..3
    int n0   = blockIdx.x * 128;

    // stage X tile (cvt -> tf32)
    for (int i = t; i < 128 * 32; i += 256) {
        int r = i >> 5, c = i & 31;
        float4 v = make_float4(0.f, 0.f, 0.f, 0.f);
        if (n0 + r < N) v = ((const float4*)xin)[(size_t)(n0 + r) * 32 + c];
        uint32_t* p = &sX[r * MSTR + c * 4];
        p[0] = f2tf32(v.x); p[1] = f2tf32(v.y); p[2] = f2tf32(v.z); p[3] = f2tf32(v.w);
    }
    // stage W1
    for (int i = t; i < 128 * 32; i += 256) {
        int r = i >> 5, c = i & 31;
        float4 v = ((const float4*)W1)[i];
        uint32_t* p = &sW[r * MSTR + c * 4];
        p[0] = f2tf32(v.x); p[1] = f2tf32(v.y); p[2] = f2tf32(v.z); p[3] = f2tf32(v.w);
    }
    __syncthreads();

    float acc[2][8][4];

    // ---- stage 1: H = sp(X @ W1^T + b1) ----
    #pragma unroll
    for (int nt = 0; nt < 8; nt++) {
        float2 b = *(const float2*)&B1[wn * 64 + nt * 8 + 2 * q];
        #pragma unroll
        for (int mt = 0; mt < 2; mt++) {
            acc[mt][nt][0] = b.x; acc[mt][nt][1] = b.y;
            acc[mt][nt][2] = b.x; acc[mt][nt][3] = b.y;
        }
    }
    #pragma unroll
    for (int kt = 0; kt < 16; kt++) {
        int k0 = kt * 8;
        uint32_t a[2][4];
        #pragma unroll
        for (int mt = 0; mt < 2; mt++) {
            int r = wm * 32 + mt * 16;
            a[mt][0] = sX[(r + g)     * MSTR + k0 + q];
            a[mt][1] = sX[(r + g + 8) * MSTR + k0 + q];
            a[mt][2] = sX[(r + g)     * MSTR + k0 + q + 4];
            a[mt][3] = sX[(r + g + 8) * MSTR + k0 + q + 4];
        }
        #pragma unroll
        for (int nt = 0; nt < 8; nt++) {
            int j = wn * 64 + nt * 8 + g;
            uint32_t b0 = sW[j * MSTR + k0 + q];
            uint32_t b1 = sW[j * MSTR + k0 + q + 4];
            mma8(acc[0][nt], a[0][0], a[0][1], a[0][2], a[0][3], b0, b1);
            mma8(acc[1][nt], a[1][0], a[1][1], a[1][2], a[1][3], b0, b1);
        }
    }
    __syncthreads();   // all reads of sX/sW done

    // write H (softplus, tf32) into sX; stage W2 into sW
    #pragma unroll
    for (int mt = 0; mt < 2; mt++) {
        #pragma unroll
        for (int nt = 0; nt < 8; nt++) {
            int r0 = wm * 32 + mt * 16 + g;
            int c0 = wn * 64 + nt * 8 + 2 * q;
            uint32_t* p0 = &sX[r0 * MSTR + c0];
            uint32_t* p1 = &sX[(r0 + 8) * MSTR + c0];
            p0[0] = f2tf32(sp(acc[mt][nt][0])); p0[1] = f2tf32(sp(acc[mt][nt][1]));
            p1[0] = f2tf32(sp(acc[mt][nt][2])); p1[1] = f2tf32(sp(acc[mt][nt][3]));
        }
    }
    for (int i = t; i < 128 * 32; i += 256) {
        int r = i >> 5, c = i & 31;
        float4 v = ((const float4*)W2)[i];
        uint32_t* p = &sW[r * MSTR + c * 4];
        p[0] = f2tf32(v.x); p[1] = f2tf32(v.y); p[2] = f2tf32(v.z); p[3] = f2tf32(v.w);
    }
    __syncthreads();

    // ---- stage 2: Y = H @ W2^T + b2 ----
    #pragma unroll
    for (int nt = 0; nt < 8; nt++) {
        float2 b = *(const float2*)&B2[wn * 64 + nt * 8 + 2 * q];
        #pragma unroll
        for (int mt = 0; mt < 2; mt++) {
            acc[mt][nt][0] = b.x; acc[mt][nt][1] = b.y;
            acc[mt][nt][2] = b.x; acc[mt][nt][3] = b.y;
        }
    }
    #pragma unroll
    for (int kt = 0; kt < 16; kt++) {
        int k0 = kt * 8;
        uint32_t a[2][4];
        #pragma unroll
        for (int mt = 0; mt < 2; mt++) {
            int r = wm * 32 + mt * 16;
            a[mt][0] = sX[(r + g)     * MSTR + k0 + q];
            a[mt][1] = sX[(r + g + 8) * MSTR + k0 + q];
            a[mt][2] = sX[(r + g)     * MSTR + k0 + q + 4];
            a[mt][3] = sX[(r + g + 8) * MSTR + k0 + q + 4];
        }
        #pragma unroll
        for (int nt = 0; nt < 8; nt++) {
            int j = wn * 64 + nt * 8 + g;
            uint32_t b0 = sW[j * MSTR + k0 + q];
            uint32_t b1 = sW[j * MSTR + k0 + q + 4];
            mma8(acc[0][nt], a[0][0], a[0][1], a[0][2], a[0][3], b0, b1);
            mma8(acc[1][nt], a[1][0], a[1][1], a[1][2], a[1][3], b0, b1);
        }
    }

    // epilogue: optional softplus, store float2 pairs directly to gmem
    #pragma unroll
    for (int mt = 0; mt < 2; mt++) {
        #pragma unroll
        for (int nt = 0; nt < 8; nt++) {
            int r0 = n0 + wm * 32 + mt * 16 + g;
            int c0 = wn * 64 + nt * 8 + 2 * q;
            float2 v0, v1;
            if (out_softplus) {
                v0 = make_float2(sp(acc[mt][nt][0]), sp(acc[mt][nt][1]));
                v1 = make_float2(sp(acc[mt][nt][2]), sp(acc[mt][nt][3]));
            } else {
                v0 = make_float2(acc[mt][nt][0], acc[mt][nt][1]);
                v1 = make_float2(acc[mt][nt][2], acc[mt][nt][3]);
            }
            if (r0 < N)     *(float2*)&xout[(size_t)r0 * HID + c0]       = v0;
            if (r0 + 8 < N) *(float2*)&xout[(size_t)(r0 + 8) * HID + c0] = v1;
        }
    }
}

// -------- graph pooling: (G,4) grid, 32 threads per block --------
__device__ __forceinline__ int lbound(const int* __restrict__ a, int n, int key) {
    int lo = 0, hi = n;
    while (lo < hi) {
        int mid = (lo + hi) >> 1;
        if (a[mid] < key) lo = mid + 1; else hi = mid;
    }
    return lo;
}

__global__ void pool_kernel(const float* __restrict__ nf, const int* __restrict__ batch,
                            float* __restrict__ gf, int N, int G) {
    int g = blockIdx.x;
    int f = blockIdx.y * 32 + threadIdx.x;
    int lo = lbound(batch, N, g);
    int hi = lbound(batch, N, g + 1);
    float acc = 0.0f;
    for (int n = lo; n < hi; n++) acc += nf[(size_t)n * HID + f];
    gf[(size_t)g * HID + f] = acc;
}

// -------- launch --------
extern "C" void kernel_launch(void* const* d_in, const int* in_sizes, int n_in,
                              void* d_out, int out_size) {
    const float* node_attr = (const float*)d_in[0];
    const float* edge_attr = (const float*)d_in[1];
    const int*   eidx      = (const int*)d_in[2];
    const int*   batch     = (const int*)d_in[3];
    const float* W1        = (const float*)d_in[4];
    const float* B1        = (const float*)d_in[5];
    const float* W2        = (const float*)d_in[6];
    const float* B2        = (const float*)d_in[7];

    int N = in_sizes[0] / HID;
    int E = in_sizes[1] / HID;
    int G = out_size / HID - N;

    const int* src = eidx;
    const int* dst = eidx + E;

    float* gf = (float*)d_out;
    float* nf = (float*)d_out + (size_t)G * HID;

    float *bufA, *bufB;
    cudaGetSymbolAddress((void**)&bufA, d_bufA);
    cudaGetSymbolAddress((void**)&bufB, d_bufB);

    cudaFuncSetAttribute(mlp_tc_kernel, cudaFuncAttributeMaxDynamicSharedMemorySize, MLP_SMEM);

    // CSR build (layer-invariant)
    clear_deg_kernel<<<(N + 255) / 256, 256>>>(N);
    hist_kernel<<<(E + 255) / 256, 256>>>(dst, E);
    scan_kernel<<<1, 1024>>>(N);
    scatter_kernel<<<(E + 255) / 256, 256>>>(src, dst, E);

    const float* x = node_attr;
    for (int l = 0; l < 3; l++) {
        agg_kernel<<<(N * 32 + 255) / 256, 256>>>(x, edge_attr, bufB, N);
        float* out = (l == 2) ? nf : bufA;
        mlp_tc_kernel<<<(N + 127) / 128, 256, MLP_SMEM>>>(
            bufB, out, W1 + (size_t)l * HID * HID, B1 + (size_t)l * HID,
            W2 + (size_t)l * HID * HID, B2 + (size_t)l * HID, N, (l < 2) ? 1 : 0);
        x = bufA;
    }
    pool_kernel<<<dim3(G, 4), 32>>>(nf, batch, gf, N, G);
}

// round 4
// speedup vs baseline: 1.8809x; 1.1739x over previous
#include <cuda_runtime.h>
#include <stdint.h>

#define HID   128
#define MAXN  50000
#define MAXE  600000

// -------- device scratch (static: allocation-free) --------
__device__ int   d_deg[MAXN];
__device__ int   d_rowptr[MAXN + 1];
__device__ int   d_cursor[MAXN];
__device__ int   d_eid[MAXE];
__device__ int   d_esrc[MAXE];
__device__ float d_bufA[MAXN * HID];
__device__ float d_bufB[MAXN * HID];

// numerically-stable softplus
__device__ __forceinline__ float sp(float v) {
    float e = __expf(-fabsf(v));
    return fmaxf(v, 0.0f) + __logf(1.0f + e);
}

__device__ __forceinline__ uint32_t f2tf32(float f) {
    uint32_t r;
    asm("cvt.rna.tf32.f32 %0, %1;" : "=r"(r) : "f"(f));
    return r;
}

__device__ __forceinline__ void mma8(float* c,
    uint32_t a0, uint32_t a1, uint32_t a2, uint32_t a3,
    uint32_t b0, uint32_t b1)
{
    asm volatile(
        "mma.sync.aligned.m16n8k8.row.col.f32.tf32.tf32.f32 "
        "{%0,%1,%2,%3}, {%4,%5,%6,%7}, {%8,%9}, {%0,%1,%2,%3};"
        : "+f"(c[0]), "+f"(c[1]), "+f"(c[2]), "+f"(c[3])
        : "r"(a0), "r"(a1), "r"(a2), "r"(a3), "r"(b0), "r"(b1));
}

// -------- CSR build --------
__global__ void clear_deg_kernel(int n) {
    int i = blockIdx.x * blockDim.x + threadIdx.x;
    if (i < n) d_deg[i] = 0;
}

__global__ void hist_kernel(const int* __restrict__ dst, int E) {
    int e = blockIdx.x * blockDim.x + threadIdx.x;
    if (e < E) atomicAdd(&d_deg[dst[e]], 1);
}

// warp-shuffle block scan, 1024 threads, serial over tiles
__global__ void scan_kernel(int n) {
    __shared__ int wsum[32];
    __shared__ int carry;
    int t = threadIdx.x;
    int lane = t & 31, w = t >> 5;
    if (t == 0) { carry = 0; d_rowptr[0] = 0; }
    __syncthreads();
    for (int base = 0; base < n; base += 1024) {
        int idx = base + t;
        int v = (idx < n) ? d_deg[idx] : 0;
        int x = v;
        #pragma unroll
        for (int off = 1; off < 32; off <<= 1) {
            int u = __shfl_up_sync(0xFFFFFFFF, x, off);
            if (lane >= off) x += u;
        }
        if (lane == 31) wsum[w] = x;
        __syncthreads();
        if (w == 0) {
            int s = wsum[lane];
            #pragma unroll
            for (int off = 1; off < 32; off <<= 1) {
                int u = __shfl_up_sync(0xFFFFFFFF, s, off);
                if (lane >= off) s += u;
            }
            wsum[lane] = s;
        }
        __syncthreads();
        int incl = x + (w ? wsum[w - 1] : 0) + carry;
        if (idx < n) {
            d_rowptr[idx + 1] = incl;
            d_cursor[idx]     = incl - v;
        }
        __syncthreads();
        if (t == 1023) carry = incl;
        __syncthreads();
    }
}

__global__ void scatter_kernel(const int* __restrict__ srcp, const int* __restrict__ dst, int E) {
    int e = blockIdx.x * blockDim.x + threadIdx.x;
    if (e < E) {
        int p = atomicAdd(&d_cursor[dst[e]], 1);
        d_eid[p]  = e;
        d_esrc[p] = srcp[e];
    }
}

// -------- edge aggregation: warp per node --------
__global__ void agg_kernel(const float* __restrict__ x, const float* __restrict__ ea,
                           float* __restrict__ out, int N) {
    int warp = (blockIdx.x * blockDim.x + threadIdx.x) >> 5;
    int lane = threadIdx.x & 31;
    if (warp >= N) return;
    const float4* x4  = (const float4*)x;
    const float4* ea4 = (const float4*)ea;
    float4 acc = x4[(size_t)warp * 32 + lane];
    int beg = d_rowptr[warp];
    int end = d_rowptr[warp + 1];
    int j = beg;
    for (; j + 1 < end; j += 2) {
        int e0 = d_eid[j],   s0 = d_esrc[j];
        int e1 = d_eid[j+1], s1 = d_esrc[j+1];
        float4 xv0 = x4[(size_t)s0 * 32 + lane];
        float4 ev0 = ea4[(size_t)e0 * 32 + lane];
        float4 xv1 = x4[(size_t)s1 * 32 + lane];
        float4 ev1 = ea4[(size_t)e1 * 32 + lane];
        acc.x += sp(xv0.x + ev0.x) + sp(xv1.x + ev1.x);
        acc.y += sp(xv0.y + ev0.y) + sp(xv1.y + ev1.y);
        acc.z += sp(xv0.z + ev0.z) + sp(xv1.z + ev1.z);
        acc.w += sp(xv0.w + ev0.w) + sp(xv1.w + ev1.w);
    }
    if (j < end) {
        int e = d_eid[j], s = d_esrc[j];
        float4 xv = x4[(size_t)s * 32 + lane];
        float4 ev = ea4[(size_t)e * 32 + lane];
        acc.x += sp(xv.x + ev.x);
        acc.y += sp(xv.y + ev.y);
        acc.z += sp(xv.z + ev.z);
        acc.w += sp(xv.w + ev.w);
    }
    ((float4*)out)[(size_t)warp * 32 + lane] = acc;
}

// -------- fused 2-layer MLP on tensor cores (tf32 mma.sync) --------
// TILE_M=64 rows/CTA, 256 threads = 8 warps: wm=wid&3 (m16 tile), wn=wid>>2 (64-col half).
// Smem rows use stride 136 words; within each 8-word K-group, words are stored
// pair-permuted (w<4 -> 2w, w>=4 -> 2(w-4)+1) so fragment pairs (q, q+4) are
// adjacent -> conflict-free LDS.64.
#define MSTR 136
#define MLP_SMEM ((64 + 128) * MSTR * 4)

__device__ __forceinline__ void stage_perm_row(uint32_t* prow, float4 v0, float4 v1) {
    uint32_t w0 = f2tf32(v0.x), w1 = f2tf32(v0.y), w2 = f2tf32(v0.z), w3 = f2tf32(v0.w);
    uint32_t w4 = f2tf32(v1.x), w5 = f2tf32(v1.y), w6 = f2tf32(v1.z), w7 = f2tf32(v1.w);
    ((uint2*)prow)[0] = make_uint2(w0, w4);
    ((uint2*)prow)[1] = make_uint2(w1, w5);
    ((uint2*)prow)[2] = make_uint2(w2, w6);
    ((uint2*)prow)[3] = make_uint2(w3, w7);
}

__global__ __launch_bounds__(256, 2) void mlp_tc_kernel(
    const float* __restrict__ xin, float* __restrict__ xout,
    const float* __restrict__ W1, const float* __restrict__ B1,
    const float* __restrict__ W2, const float* __restrict__ B2,
    int N, int out_softplus)
{
    extern __shared__ uint32_t smu[];
    uint32_t* sX = smu;               // 64 x MSTR
    uint32_t* sW = smu + 64 * MSTR;   // 128 x MSTR

    int t    = threadIdx.x;
    int lane = t & 31;
    int wid  = t >> 5;
    int wm   = wid & 3;
    int wn   = wid >> 2;
    int g    = lane >> 2;  // 0..7
    int q    = lane & 3;   // 0..3
    int n0   = blockIdx.x * 64;

    // stage X tile (64 rows x 16 groups)
    for (int i = t; i < 64 * 16; i += 256) {
        int r = i >> 4, grp = i & 15;
        float4 v0 = make_float4(0.f,0.f,0.f,0.f), v1 = v0;
        if (n0 + r < N) {
            const float4* p = (const float4*)xin + (size_t)(n0 + r) * 32 + grp * 2;
            v0 = p[0]; v1 = p[1];
        }
        stage_perm_row(&sX[r * MSTR + grp * 8], v0, v1);
    }
    // stage W1 (128 rows x 16 groups)
    for (int i = t; i < 128 * 16; i += 256) {
        int r = i >> 4, grp = i & 15;
        const float4* p = (const float4*)W1 + (size_t)r * 32 + grp * 2;
        stage_perm_row(&sW[r * MSTR + grp * 8], p[0], p[1]);
    }
    __syncthreads();

    float acc[8][4];
    int ar0 = (wm * 16 + g) * MSTR + 2 * q;       // A row g
    int ar1 = (wm * 16 + g + 8) * MSTR + 2 * q;   // A row g+8
    int br  = (wn * 64 + g) * MSTR + 2 * q;       // B base row

    // ---- stage 1: H = sp(X @ W1^T + b1) ----
    #pragma unroll
    for (int nt = 0; nt < 8; nt++) {
        float2 b = *(const float2*)&B1[wn * 64 + nt * 8 + 2 * q];
        acc[nt][0] = b.x; acc[nt][1] = b.y; acc[nt][2] = b.x; acc[nt][3] = b.y;
    }
    #pragma unroll
    for (int kt = 0; kt < 16; kt++) {
        int k8 = kt * 8;
        uint2 alo = *(uint2*)&sX[ar0 + k8];
        uint2 ahi = *(uint2*)&sX[ar1 + k8];
        #pragma unroll
        for (int nt = 0; nt < 8; nt++) {
            uint2 bb = *(uint2*)&sW[br + nt * 8 * MSTR + k8];
            mma8(acc[nt], alo.x, ahi.x, alo.y, ahi.y, bb.x, bb.y);
        }
    }
    __syncthreads();   // all reads of sX/sW done

    // write H (softplus -> tf32, permuted) into sX; stage W2 into sW
    #pragma unroll
    for (int nt = 0; nt < 8; nt++) {
        int grp = wn * 8 + nt;
        int pos0 = (q < 2) ? 4 * q : 4 * q - 7;   // col 2q
        uint32_t* p0 = &sX[(wm * 16 + g) * MSTR + grp * 8 + pos0];
        uint32_t* p1 = &sX[(wm * 16 + g + 8) * MSTR + grp * 8 + pos0];
        p0[0] = f2tf32(sp(acc[nt][0])); p0[2] = f2tf32(sp(acc[nt][1]));
        p1[0] = f2tf32(sp(acc[nt][2])); p1[2] = f2tf32(sp(acc[nt][3]));
    }
    for (int i = t; i < 128 * 16; i += 256) {
        int r = i >> 4, grp = i & 15;
        const float4* p = (const float4*)W2 + (size_t)r * 32 + grp * 2;
        stage_perm_row(&sW[r * MSTR + grp * 8], p[0], p[1]);
    }
    __syncthreads();

    // ---- stage 2: Y = H @ W2^T + b2 ----
    #pragma unroll
    for (int nt = 0; nt < 8; nt++) {
        float2 b = *(const float2*)&B2[wn * 64 + nt * 8 + 2 * q];
        acc[nt][0] = b.x; acc[nt][1] = b.y; acc[nt][2] = b.x; acc[nt][3] = b.y;
    }
    #pragma unroll
    for (int kt = 0; kt < 16; kt++) {
        int k8 = kt * 8;
        uint2 alo = *(uint2*)&sX[ar0 + k8];
        uint2 ahi = *(uint2*)&sX[ar1 + k8];
        #pragma unroll
        for (int nt = 0; nt < 8; nt++) {
            uint2 bb = *(uint2*)&sW[br + nt * 8 * MSTR + k8];
            mma8(acc[nt], alo.x, ahi.x, alo.y, ahi.y, bb.x, bb.y);
        }
    }

    // epilogue: optional softplus, float2 stores to gmem
    int r0 = n0 + wm * 16 + g;
    #pragma unroll
    for (int nt = 0; nt < 8; nt++) {
        int c0 = wn * 64 + nt * 8 + 2 * q;
        float2 v0, v1;
        if (out_softplus) {
            v0 = make_float2(sp(acc[nt][0]), sp(acc[nt][1]));
            v1 = make_float2(sp(acc[nt][2]), sp(acc[nt][3]));
        } else {
            v0 = make_float2(acc[nt][0], acc[nt][1]);
            v1 = make_float2(acc[nt][2], acc[nt][3]);
        }
        if (r0 < N)     *(float2*)&xout[(size_t)r0 * HID + c0]       = v0;
        if (r0 + 8 < N) *(float2*)&xout[(size_t)(r0 + 8) * HID + c0] = v1;
    }
}

// -------- graph pooling --------
__device__ __forceinline__ int lbound(const int* __restrict__ a, int n, int key) {
    int lo = 0, hi = n;
    while (lo < hi) {
        int mid = (lo + hi) >> 1;
        if (a[mid] < key) lo = mid + 1; else hi = mid;
    }
    return lo;
}

__global__ void pool_kernel(const float* __restrict__ nf, const int* __restrict__ batch,
                            float* __restrict__ gf, int N, int G) {
    int g = blockIdx.x;
    int f = blockIdx.y * 32 + threadIdx.x;
    int lo = lbound(batch, N, g);
    int hi = lbound(batch, N, g + 1);
    float acc = 0.0f;
    for (int n = lo; n < hi; n++) acc += nf[(size_t)n * HID + f];
    gf[(size_t)g * HID + f] = acc;
}

// -------- launch --------
extern "C" void kernel_launch(void* const* d_in, const int* in_sizes, int n_in,
                              void* d_out, int out_size) {
    const float* node_attr = (const float*)d_in[0];
    const float* edge_attr = (const float*)d_in[1];
    const int*   eidx      = (const int*)d_in[2];
    const int*   batch     = (const int*)d_in[3];
    const float* W1        = (const float*)d_in[4];
    const float* B1        = (const float*)d_in[5];
    const float* W2        = (const float*)d_in[6];
    const float* B2        = (const float*)d_in[7];

    int N = in_sizes[0] / HID;
    int E = in_sizes[1] / HID;
    int G = out_size / HID - N;

    const int* src = eidx;
    const int* dst = eidx + E;

    float* gf = (float*)d_out;
    float* nf = (float*)d_out + (size_t)G * HID;

    float *bufA, *bufB;
    cudaGetSymbolAddress((void**)&bufA, d_bufA);
    cudaGetSymbolAddress((void**)&bufB, d_bufB);

    cudaFuncSetAttribute(mlp_tc_kernel, cudaFuncAttributeMaxDynamicSharedMemorySize, MLP_SMEM);

    // CSR build (layer-invariant)
    clear_deg_kernel<<<(N + 255) / 256, 256>>>(N);
    hist_kernel<<<(E + 255) / 256, 256>>>(dst, E);
    scan_kernel<<<1, 1024>>>(N);
    scatter_kernel<<<(E + 255) / 256, 256>>>(src, dst, E);

    const float* x = node_attr;
    for (int l = 0; l < 3; l++) {
        agg_kernel<<<(N * 32 + 255) / 256, 256>>>(x, edge_attr, bufB, N);
        float* out = (l == 2) ? nf : bufA;
        mlp_tc_kernel<<<(N + 63) / 64, 256, MLP_SMEM>>>(
            bufB, out, W1 + (size_t)l * HID * HID, B1 + (size_t)l * HID,
            W2 + (size_t)l * HID * HID, B2 + (size_t)l * HID, N, (l < 2) ? 1 : 0);
        x = bufA;
    }
    pool_kernel<<<dim3(G, 4), 32>>>(nf, batch, gf, N, G);
}